// round 1
// baseline (speedup 1.0000x reference)
#include <cuda_runtime.h>
#include <cuda_bf16.h>
#include <cstdint>

// Problem shape (fixed by setup_inputs)
#define M_TOTAL 16384      // B*T = 8*2048
#define D_DIM   4096       // d
#define RANK    819        // int(4096*0.2)

// Tiling
#define BM 128
#define BN 128
#define BK 8
#define TM 8
#define TN 8
#define NTHREADS 256       // (BM/TM)*(BN/TN)

// Scratch for intermediate Y = x @ (U*S)  : 16384 x 819 fp32 (~53.7 MB)
__device__ float g_Y[(size_t)M_TOTAL * RANK];

// ---------------------------------------------------------------------------
// Kernel 1: Y[m,r] = sum_k X[m,k] * U[k,r] * S[r]
//   X: (M, K=4096) row-major, fully aligned -> float4 loads
//   U: (K, N=819) row-major, row stride 819 (unaligned) -> scalar guarded loads
// ---------------------------------------------------------------------------
__global__ __launch_bounds__(NTHREADS)
void gemm_xUS(const float* __restrict__ X,
              const float* __restrict__ U,
              const float* __restrict__ S,
              float* __restrict__ Y)
{
    const int M = M_TOTAL, N = RANK, K = D_DIM;

    __shared__ float As[BK][BM];   // transposed A tile
    __shared__ float Bs[BK][BN];
    __shared__ float Ss[BN];

    const int bm = blockIdx.y * BM;
    const int bn = blockIdx.x * BN;
    const int tid = threadIdx.x;
    const int tr = tid / (BN / TN);   // 0..15
    const int tc = tid % (BN / TN);   // 0..15

    // A-tile load mapping: one float4 along K per thread
    const int aRow = tid / 2;          // 0..127
    const int aCol = (tid % 2) * 4;    // 0 or 4
    // B-tile load mapping: 4 consecutive columns per thread
    const int bRow = tid / 32;         // 0..7
    const int bCol = (tid % 32) * 4;   // 0..124

    // Cache S slice for this block's column range (constant across k-tiles)
    if (tid < BN) {
        int n = bn + tid;
        Ss[tid] = (n < N) ? S[n] : 0.0f;
    }
    __syncthreads();

    float acc[TM][TN];
    #pragma unroll
    for (int i = 0; i < TM; i++)
        #pragma unroll
        for (int j = 0; j < TN; j++)
            acc[i][j] = 0.0f;

    float regA[TM], regB[TN];

    for (int k0 = 0; k0 < K; k0 += BK) {
        // Load A tile (no guards: M,K are multiples of tile dims, aligned)
        float4 a4 = *reinterpret_cast<const float4*>(
            X + (size_t)(bm + aRow) * K + k0 + aCol);
        As[aCol + 0][aRow] = a4.x;
        As[aCol + 1][aRow] = a4.y;
        As[aCol + 2][aRow] = a4.z;
        As[aCol + 3][aRow] = a4.w;

        // Load B tile = U * S (scalar, column-guarded; k always in-bounds)
        const int k = k0 + bRow;
        #pragma unroll
        for (int j = 0; j < 4; j++) {
            int lc = bCol + j;
            int n  = bn + lc;
            float v = 0.0f;
            if (n < N) v = U[(size_t)k * N + n] * Ss[lc];
            Bs[bRow][lc] = v;
        }
        __syncthreads();

        #pragma unroll
        for (int kk = 0; kk < BK; kk++) {
            #pragma unroll
            for (int i = 0; i < TM; i++) regA[i] = As[kk][tr * TM + i];
            #pragma unroll
            for (int j = 0; j < TN; j++) regB[j] = Bs[kk][tc * TN + j];
            #pragma unroll
            for (int i = 0; i < TM; i++)
                #pragma unroll
                for (int j = 0; j < TN; j++)
                    acc[i][j] = fmaf(regA[i], regB[j], acc[i][j]);
        }
        __syncthreads();
    }

    // Store Y (column-guarded)
    #pragma unroll
    for (int i = 0; i < TM; i++) {
        int m = bm + tr * TM + i;
        #pragma unroll
        for (int j = 0; j < TN; j++) {
            int n = bn + tc * TN + j;
            if (n < N) Y[(size_t)m * N + n] = acc[i][j];
        }
    }
}

// ---------------------------------------------------------------------------
// Kernel 2: Out[m,n] = sum_r Y[m,r] * V[r,n] + alpha * X[m,n]
//   Y: (M, R=819) row-major (unaligned rows) -> scalar guarded loads
//   V: (R, N=4096) row-major, aligned -> float4 loads, row-guarded on r
//   X/Out: (M, N=4096) aligned -> float4 epilogue
// ---------------------------------------------------------------------------
__global__ __launch_bounds__(NTHREADS)
void gemm_YV_plus_x(const float* __restrict__ Y,
                    const float* __restrict__ V,
                    const float* __restrict__ X,
                    const float* __restrict__ alpha_p,
                    float* __restrict__ Out)
{
    const int N = D_DIM, R = RANK;
    const int KTILES = (R + BK - 1) / BK;   // 103

    __shared__ float As[BK][BM];
    __shared__ float Bs[BK][BN];

    const int bm = blockIdx.y * BM;
    const int bn = blockIdx.x * BN;
    const int tid = threadIdx.x;
    const int tr = tid / (BN / TN);
    const int tc = tid % (BN / TN);

    const int aRow = tid / 2;
    const int aCol = (tid % 2) * 4;
    const int bRow = tid / 32;
    const int bCol = (tid % 32) * 4;

    float acc[TM][TN];
    #pragma unroll
    for (int i = 0; i < TM; i++)
        #pragma unroll
        for (int j = 0; j < TN; j++)
            acc[i][j] = 0.0f;

    float regA[TM], regB[TN];

    for (int t = 0; t < KTILES; t++) {
        const int k0 = t * BK;

        // Load A tile from Y (scalar, k-guarded; rows of Y are not 16B aligned)
        #pragma unroll
        for (int j = 0; j < 4; j++) {
            int k = k0 + aCol + j;
            float v = 0.0f;
            if (k < R) v = Y[(size_t)(bm + aRow) * R + k];
            As[aCol + j][aRow] = v;
        }

        // Load B tile from V (float4, row-guarded on k)
        {
            int k = k0 + bRow;
            float4 b4 = make_float4(0.f, 0.f, 0.f, 0.f);
            if (k < R) {
                b4 = *reinterpret_cast<const float4*>(
                    V + (size_t)k * N + bn + bCol);
            }
            Bs[bRow][bCol + 0] = b4.x;
            Bs[bRow][bCol + 1] = b4.y;
            Bs[bRow][bCol + 2] = b4.z;
            Bs[bRow][bCol + 3] = b4.w;
        }
        __syncthreads();

        #pragma unroll
        for (int kk = 0; kk < BK; kk++) {
            #pragma unroll
            for (int i = 0; i < TM; i++) regA[i] = As[kk][tr * TM + i];
            #pragma unroll
            for (int j = 0; j < TN; j++) regB[j] = Bs[kk][tc * TN + j];
            #pragma unroll
            for (int i = 0; i < TM; i++)
                #pragma unroll
                for (int j = 0; j < TN; j++)
                    acc[i][j] = fmaf(regA[i], regB[j], acc[i][j]);
        }
        __syncthreads();
    }

    const float alpha = *alpha_p;

    // Epilogue: Out = acc + alpha * X  (fully aligned, vectorized)
    #pragma unroll
    for (int i = 0; i < TM; i++) {
        const int m = bm + tr * TM + i;
        const size_t base = (size_t)m * N + bn + tc * TN;
        float4 x0 = *reinterpret_cast<const float4*>(X + base);
        float4 x1 = *reinterpret_cast<const float4*>(X + base + 4);
        float4 o0, o1;
        o0.x = fmaf(alpha, x0.x, acc[i][0]);
        o0.y = fmaf(alpha, x0.y, acc[i][1]);
        o0.z = fmaf(alpha, x0.z, acc[i][2]);
        o0.w = fmaf(alpha, x0.w, acc[i][3]);
        o1.x = fmaf(alpha, x1.x, acc[i][4]);
        o1.y = fmaf(alpha, x1.y, acc[i][5]);
        o1.z = fmaf(alpha, x1.z, acc[i][6]);
        o1.w = fmaf(alpha, x1.w, acc[i][7]);
        *reinterpret_cast<float4*>(Out + base)     = o0;
        *reinterpret_cast<float4*>(Out + base + 4) = o1;
    }
}

extern "C" void kernel_launch(void* const* d_in, const int* in_sizes, int n_in,
                              void* d_out, int out_size)
{
    const float* x     = (const float*)d_in[0];  // (8,2048,4096)
    const float* U     = (const float*)d_in[1];  // (4096,819)
    const float* S     = (const float*)d_in[2];  // (819,)
    const float* V     = (const float*)d_in[3];  // (819,4096)
    const float* alpha = (const float*)d_in[4];  // scalar
    float* out = (float*)d_out;

    float* Yp = nullptr;
    cudaGetSymbolAddress((void**)&Yp, g_Y);

    // Kernel 1: Y = x @ (U*S)   grid: N-tiles x M-tiles
    {
        dim3 grid((RANK + BN - 1) / BN, M_TOTAL / BM);   // 7 x 128
        gemm_xUS<<<grid, NTHREADS>>>(x, U, S, Yp);
    }
    // Kernel 2: out = Y @ V + alpha*x
    {
        dim3 grid(D_DIM / BN, M_TOTAL / BM);             // 32 x 128
        gemm_YV_plus_x<<<grid, NTHREADS>>>(Yp, V, x, alpha, out);
    }
}

// round 2
// speedup vs baseline: 3.6444x; 3.6444x over previous
#include <cuda_runtime.h>
#include <cuda_bf16.h>
#include <cstdint>

// Problem shape (fixed by setup_inputs)
#define M_TOTAL 16384      // B*T
#define D_DIM   4096
#define RANK    819

// Tiling
#define BM 128
#define BN 128
#define BK 32
#define NTHREADS 256       // 8 warps: 2 (M) x 4 (N), warp tile 64x32

#define A_PAD 36           // conflict-free for A frag loads (4*g disjoint quads)
#define B_PAD 136          // conflict-free for B frag loads (8*k disjoint octets)

// Scratch for Y = x @ (U*S): 16384 x 819 fp32
__device__ float g_Y[(size_t)M_TOTAL * RANK];

__device__ __forceinline__ uint32_t f2tf32(float f) {
    uint32_t u;
    asm("cvt.rna.tf32.f32 %0, %1;" : "=r"(u) : "f"(f));
    return u;
}

__device__ __forceinline__ void mma8(float c[4],
                                     uint32_t a0, uint32_t a1, uint32_t a2, uint32_t a3,
                                     uint32_t b0, uint32_t b1) {
    asm volatile(
        "mma.sync.aligned.m16n8k8.row.col.f32.tf32.tf32.f32 "
        "{%0,%1,%2,%3}, {%4,%5,%6,%7}, {%8,%9}, {%0,%1,%2,%3};"
        : "+f"(c[0]), "+f"(c[1]), "+f"(c[2]), "+f"(c[3])
        : "r"(a0), "r"(a1), "r"(a2), "r"(a3), "r"(b0), "r"(b1));
}

// ---------------------------------------------------------------------------
// Kernel 1: Y[m,r] = sum_k X[m,k] * U[k,r] * S[r]
// ---------------------------------------------------------------------------
__global__ __launch_bounds__(NTHREADS)
void gemm_xUS(const float* __restrict__ X,
              const float* __restrict__ U,
              const float* __restrict__ S,
              float* __restrict__ Y)
{
    __shared__ uint32_t As[BM][A_PAD];   // [m][k], tf32 bits
    __shared__ uint32_t Bs[BK][B_PAD];   // [k][n], tf32 bits

    const int bm = blockIdx.y * BM;
    const int bn = blockIdx.x * BN;
    const int tid = threadIdx.x;
    const int wid = tid >> 5;
    const int lane = tid & 31;
    const int gid = lane >> 2;
    const int tg = lane & 3;
    const int warpM = wid >> 2;          // 0..1
    const int warpN = wid & 3;           // 0..3

    // Global-load mappings
    const int aRow = tid >> 3;           // 0..31 (then +32,+64,+96)
    const int aCol = (tid & 7) * 4;
    const int bCol = tid & 127;          // fixed column for U loads
    const int bRow0 = tid >> 7;          // 0..1 (then step 2)

    // Preload S for this thread's fixed column (constant over k-tiles)
    const int nB = bn + bCol;
    const float sB = (nB < RANK) ? S[nB] : 0.0f;

    float c[4][4][4];
    #pragma unroll
    for (int i = 0; i < 4; i++)
        #pragma unroll
        for (int j = 0; j < 4; j++)
            #pragma unroll
            for (int v = 0; v < 4; v++) c[i][j][v] = 0.0f;

    for (int k0 = 0; k0 < D_DIM; k0 += BK) {
        __syncthreads();
        // A tile: X (aligned), 4x float4 per thread
        #pragma unroll
        for (int i = 0; i < 4; i++) {
            const int r = aRow + 32 * i;
            float4 v = *reinterpret_cast<const float4*>(
                X + (size_t)(bm + r) * D_DIM + k0 + aCol);
            As[r][aCol + 0] = f2tf32(v.x);
            As[r][aCol + 1] = f2tf32(v.y);
            As[r][aCol + 2] = f2tf32(v.z);
            As[r][aCol + 3] = f2tf32(v.w);
        }
        // B tile: U * S (column-guarded scalars, coalesced per row)
        #pragma unroll
        for (int i = 0; i < 16; i++) {
            const int kr = bRow0 + 2 * i;
            float v = 0.0f;
            if (nB < RANK) v = U[(size_t)(k0 + kr) * RANK + nB] * sB;
            Bs[kr][bCol] = f2tf32(v);
        }
        __syncthreads();

        #pragma unroll
        for (int ks = 0; ks < 4; ks++) {
            const int cb = ks * 8;
            uint32_t af[4][4];
            #pragma unroll
            for (int i = 0; i < 4; i++) {
                const int r0 = warpM * 64 + i * 16 + gid;
                af[i][0] = As[r0][cb + tg];
                af[i][1] = As[r0 + 8][cb + tg];
                af[i][2] = As[r0][cb + tg + 4];
                af[i][3] = As[r0 + 8][cb + tg + 4];
            }
            uint32_t bf[4][2];
            #pragma unroll
            for (int j = 0; j < 4; j++) {
                const int col = warpN * 32 + j * 8 + gid;
                bf[j][0] = Bs[cb + tg][col];
                bf[j][1] = Bs[cb + tg + 4][col];
            }
            #pragma unroll
            for (int i = 0; i < 4; i++)
                #pragma unroll
                for (int j = 0; j < 4; j++)
                    mma8(c[i][j], af[i][0], af[i][1], af[i][2], af[i][3],
                         bf[j][0], bf[j][1]);
        }
    }

    // Store Y (column-guarded)
    #pragma unroll
    for (int i = 0; i < 4; i++) {
        const int r0 = bm + warpM * 64 + i * 16 + gid;
        #pragma unroll
        for (int j = 0; j < 4; j++) {
            const int n0 = bn + warpN * 32 + j * 8 + tg * 2;
            if (n0 < RANK)     Y[(size_t)r0 * RANK + n0]           = c[i][j][0];
            if (n0 + 1 < RANK) Y[(size_t)r0 * RANK + n0 + 1]       = c[i][j][1];
            if (n0 < RANK)     Y[(size_t)(r0 + 8) * RANK + n0]     = c[i][j][2];
            if (n0 + 1 < RANK) Y[(size_t)(r0 + 8) * RANK + n0 + 1] = c[i][j][3];
        }
    }
}

// ---------------------------------------------------------------------------
// Kernel 2: Out[m,n] = sum_r Y[m,r] * V[r,n] + alpha * X[m,n]
// ---------------------------------------------------------------------------
__global__ __launch_bounds__(NTHREADS)
void gemm_YV_plus_x(const float* __restrict__ Yg,
                    const float* __restrict__ V,
                    const float* __restrict__ X,
                    const float* __restrict__ alpha_p,
                    float* __restrict__ Out)
{
    __shared__ uint32_t As[BM][A_PAD];
    __shared__ uint32_t Bs[BK][B_PAD];

    const int bm = blockIdx.y * BM;
    const int bn = blockIdx.x * BN;
    const int tid = threadIdx.x;
    const int wid = tid >> 5;
    const int lane = tid & 31;
    const int gid = lane >> 2;
    const int tg = lane & 3;
    const int warpM = wid >> 2;
    const int warpN = wid & 3;

    // Global-load mappings
    const int aCol = tid & 31;           // k index within tile (coalesced)
    const int aRow0 = tid >> 5;          // 0..7 (then step 8)
    const int bRow = tid >> 3;           // 0..31
    const int bCol = (tid & 7) * 4;      // then +32,+64,+96

    float c[4][4][4];
    #pragma unroll
    for (int i = 0; i < 4; i++)
        #pragma unroll
        for (int j = 0; j < 4; j++)
            #pragma unroll
            for (int v = 0; v < 4; v++) c[i][j][v] = 0.0f;

    const int KT = (RANK + BK - 1) / BK;   // 26
    for (int t = 0; t < KT; t++) {
        const int k0 = t * BK;
        __syncthreads();
        // A tile: Y (scalar, k-guarded; coalesced 128B per row)
        const bool kOK = (k0 + aCol) < RANK;
        #pragma unroll
        for (int i = 0; i < 16; i++) {
            const int r = aRow0 + 8 * i;
            float v = 0.0f;
            if (kOK) v = Yg[(size_t)(bm + r) * RANK + k0 + aCol];
            As[r][aCol] = f2tf32(v);
        }
        // B tile: V (float4, row-guarded on k)
        {
            const bool rOK = (k0 + bRow) < RANK;
            #pragma unroll
            for (int i = 0; i < 4; i++) {
                const int cc = bCol + 32 * i;
                float4 v = make_float4(0.f, 0.f, 0.f, 0.f);
                if (rOK)
                    v = *reinterpret_cast<const float4*>(
                        V + (size_t)(k0 + bRow) * D_DIM + bn + cc);
                Bs[bRow][cc + 0] = f2tf32(v.x);
                Bs[bRow][cc + 1] = f2tf32(v.y);
                Bs[bRow][cc + 2] = f2tf32(v.z);
                Bs[bRow][cc + 3] = f2tf32(v.w);
            }
        }
        __syncthreads();

        #pragma unroll
        for (int ks = 0; ks < 4; ks++) {
            const int cb = ks * 8;
            uint32_t af[4][4];
            #pragma unroll
            for (int i = 0; i < 4; i++) {
                const int r0 = warpM * 64 + i * 16 + gid;
                af[i][0] = As[r0][cb + tg];
                af[i][1] = As[r0 + 8][cb + tg];
                af[i][2] = As[r0][cb + tg + 4];
                af[i][3] = As[r0 + 8][cb + tg + 4];
            }
            uint32_t bf[4][2];
            #pragma unroll
            for (int j = 0; j < 4; j++) {
                const int col = warpN * 32 + j * 8 + gid;
                bf[j][0] = Bs[cb + tg][col];
                bf[j][1] = Bs[cb + tg + 4][col];
            }
            #pragma unroll
            for (int i = 0; i < 4; i++)
                #pragma unroll
                for (int j = 0; j < 4; j++)
                    mma8(c[i][j], af[i][0], af[i][1], af[i][2], af[i][3],
                         bf[j][0], bf[j][1]);
        }
    }

    const float alpha = *alpha_p;

    // Epilogue: Out = c + alpha * X (float2 per C-pair, aligned: col even)
    #pragma unroll
    for (int i = 0; i < 4; i++) {
        const int r0 = bm + warpM * 64 + i * 16 + gid;
        #pragma unroll
        for (int j = 0; j < 4; j++) {
            const int n0 = bn + warpN * 32 + j * 8 + tg * 2;
            {
                const size_t off = (size_t)r0 * D_DIM + n0;
                float2 xv = *reinterpret_cast<const float2*>(X + off);
                float2 ov;
                ov.x = fmaf(alpha, xv.x, c[i][j][0]);
                ov.y = fmaf(alpha, xv.y, c[i][j][1]);
                *reinterpret_cast<float2*>(Out + off) = ov;
            }
            {
                const size_t off = (size_t)(r0 + 8) * D_DIM + n0;
                float2 xv = *reinterpret_cast<const float2*>(X + off);
                float2 ov;
                ov.x = fmaf(alpha, xv.x, c[i][j][2]);
                ov.y = fmaf(alpha, xv.y, c[i][j][3]);
                *reinterpret_cast<float2*>(Out + off) = ov;
            }
        }
    }
}

extern "C" void kernel_launch(void* const* d_in, const int* in_sizes, int n_in,
                              void* d_out, int out_size)
{
    const float* x     = (const float*)d_in[0];
    const float* U     = (const float*)d_in[1];
    const float* S     = (const float*)d_in[2];
    const float* V     = (const float*)d_in[3];
    const float* alpha = (const float*)d_in[4];
    float* out = (float*)d_out;

    float* Yp = nullptr;
    cudaGetSymbolAddress((void**)&Yp, g_Y);

    {
        dim3 grid((RANK + BN - 1) / BN, M_TOTAL / BM);   // 7 x 128
        gemm_xUS<<<grid, NTHREADS>>>(x, U, S, Yp);
    }
    {
        dim3 grid(D_DIM / BN, M_TOTAL / BM);             // 32 x 128
        gemm_YV_plus_x<<<grid, NTHREADS>>>(Yp, V, x, alpha, out);
    }
}